// round 14
// baseline (speedup 1.0000x reference)
#include <cuda_runtime.h>
#include <cuda_bf16.h>
#include <math.h>

#define N_NODES   50000
#define N_HEDGES  100000
#define E_INC     800000
#define N_GRAPHS  512
#define IN_DIM    92
#define H_DIM     64
#define HOUT      128
#define HEDGE_DIM 35
#define Z_DIM     163   // 64 + 35 + 64 (logical)
#define Z_PITCH   164   // padded smem row pitch (16B-aligned rows)
#define N_LAYERS  3

// W_s layout: [k][quarter q padded to 36 floats] -> conflict-free LDS.128
#define WQ_PITCH  36
#define WK_PITCH  144

#define NBH 98            // ceil(100000/1024)
#define NBN 49            // ceil(50000/1024)
#define NBT (NBH + NBN)   // 147

typedef unsigned long long ull;

// ---------------- scratch (device globals; no allocation allowed) ----------
__device__ float g_hA[N_NODES * H_DIM];
__device__ float g_hB[N_NODES * H_DIM];
__device__ float g_hxs[N_HEDGES * H_DIM];
__device__ float g_nodeagg[N_NODES * H_DIM];
__device__ float g_attragg[N_NODES * HEDGE_DIM];

__device__ int g_hcnt[N_HEDGES];
__device__ int g_ncnt[N_NODES];
__device__ int g_hoff[N_HEDGES + 1];
__device__ int g_noff[N_NODES + 1];
__device__ int g_hfill[N_HEDGES];
__device__ int g_nfill[N_NODES];
__device__ int g_csr_h[E_INC];   // node ids grouped by hedge
__device__ int g_csr_n[E_INC];   // hedge ids grouped by node
__device__ int g_part[256];

// ---------------- helpers ----------------
__device__ __forceinline__ float softplusf(float x) {
    return fmaxf(x, 0.f) + log1pf(expf(-fabsf(x)));
}
__device__ __forceinline__ float sigmoidf(float x) {
    return 1.f / (1.f + expf(-x));
}
__device__ __forceinline__ ull packdup(float x) {
    ull r;
    asm("mov.b64 %0, {%1, %2};" : "=l"(r)
        : "r"(__float_as_uint(x)), "r"(__float_as_uint(x)));
    return r;
}
__device__ __forceinline__ float2 unpk(ull v) {
    unsigned a, b;
    asm("mov.b64 {%0, %1}, %2;" : "=r"(a), "=r"(b) : "l"(v));
    return make_float2(__uint_as_float(a), __uint_as_float(b));
}
__device__ __forceinline__ void fma2(ull &c, ull a, ull b) {
    asm("fma.rn.f32x2 %0, %1, %2, %0;" : "+l"(c) : "l"(a), "l"(b));
}

// ---------------- CSR construction ----------------
__global__ void count_kernel(const int *__restrict__ node_idx,
                             const int *__restrict__ hedge_idx) {
    int e = blockIdx.x * blockDim.x + threadIdx.x;
    if (e < E_INC) {
        atomicAdd(&g_hcnt[hedge_idx[e]], 1);
        atomicAdd(&g_ncnt[node_idx[e]], 1);
    }
}

__global__ void __launch_bounds__(1024) scan_partial_both() {
    __shared__ int s[1024];
    int b = blockIdx.x;
    const int *cnt = (b < NBH) ? g_hcnt : g_ncnt;
    int n = (b < NBH) ? N_HEDGES : N_NODES;
    int chunk = (b < NBH) ? b : b - NBH;
    int i = chunk * 1024 + threadIdx.x;
    s[threadIdx.x] = (i < n) ? cnt[i] : 0;
    __syncthreads();
    for (int d = 512; d > 0; d >>= 1) {
        if (threadIdx.x < d) s[threadIdx.x] += s[threadIdx.x + d];
        __syncthreads();
    }
    if (threadIdx.x == 0) g_part[b] = s[0];
}

__global__ void __launch_bounds__(1024) scan_final_both() {
    __shared__ int s[1024];
    __shared__ int red[32];
    __shared__ int sbase;
    int b = blockIdx.x;
    bool isH = b < NBH;
    const int *cnt = isH ? g_hcnt : g_ncnt;
    int *off  = isH ? g_hoff : g_noff;
    int *fill = isH ? g_hfill : g_nfill;
    int n     = isH ? N_HEDGES : N_NODES;
    int start = isH ? 0 : NBH;
    int chunk = isH ? b : b - NBH;
    int t = threadIdx.x;

    int contrib = (t < NBT && t >= start && t < b) ? g_part[t] : 0;
#pragma unroll
    for (int o = 16; o > 0; o >>= 1)
        contrib += __shfl_down_sync(0xffffffffu, contrib, o);
    if ((t & 31) == 0) red[t >> 5] = contrib;
    __syncthreads();
    if (t == 0) {
        int acc = 0;
#pragma unroll
        for (int i = 0; i < 32; i++) acc += red[i];
        sbase = acc;
    }
    __syncthreads();

    int i = chunk * 1024 + t;
    int v = (i < n) ? cnt[i] : 0;
    s[t] = v;
    __syncthreads();
    for (int d = 1; d < 1024; d <<= 1) {
        int x = (t >= d) ? s[t - d] : 0;
        __syncthreads();
        s[t] += x;
        __syncthreads();
    }
    int excl = s[t] - v + sbase;
    if (i < n) {
        off[i] = excl;
        fill[i] = excl;
        if (i == n - 1) off[n] = excl + v;
    }
}

__global__ void fill_kernel(const int *__restrict__ node_idx,
                            const int *__restrict__ hedge_idx) {
    int e = blockIdx.x * blockDim.x + threadIdx.x;
    if (e < E_INC) {
        int nd = node_idx[e], he = hedge_idx[e];
        int p = atomicAdd(&g_hfill[he], 1);
        g_csr_h[p] = nd;
        int p2 = atomicAdd(&g_nfill[nd], 1);
        g_csr_n[p2] = he;
        if (e < N_HEDGES) g_hcnt[e] = 0;
        if (e < N_NODES)  g_ncnt[e] = 0;
    }
}

// ---------------- embed: h = x @ W_embed + b (conflict-free smem) ---------
__global__ void __launch_bounds__(256) embed_kernel(
    const float *__restrict__ x, const float *__restrict__ W,
    const float *__restrict__ b, float *__restrict__ h) {
    __shared__ float W_s[IN_DIM * H_DIM];
    __shared__ float x_s[16][IN_DIM];
    const int tid = threadIdx.x;
    for (int i = tid; i < IN_DIM * H_DIM; i += 256) W_s[i] = W[i];
    {
        const int nbase = blockIdx.x * 16;
        for (int idx = tid; idx < 16 * 23; idx += 256) {
            int n = idx / 23, k4 = idx - n * 23;
            *(float4 *)(&x_s[n][k4 * 4]) =
                *(const float4 *)(x + (nbase + n) * IN_DIM + k4 * 4);
        }
    }
    __syncthreads();
    const int col = tid & 63, sub = tid >> 6;
    float a0, a1, a2, a3;
    a0 = a1 = a2 = a3 = b[col];
#pragma unroll
    for (int k4 = 0; k4 < 23; k4++) {
        float4 x0 = *(const float4 *)(&x_s[sub * 4 + 0][k4 * 4]);
        float4 x1 = *(const float4 *)(&x_s[sub * 4 + 1][k4 * 4]);
        float4 x2 = *(const float4 *)(&x_s[sub * 4 + 2][k4 * 4]);
        float4 x3 = *(const float4 *)(&x_s[sub * 4 + 3][k4 * 4]);
        float w0 = W_s[(k4 * 4 + 0) * 64 + col];
        float w1 = W_s[(k4 * 4 + 1) * 64 + col];
        float w2 = W_s[(k4 * 4 + 2) * 64 + col];
        float w3 = W_s[(k4 * 4 + 3) * 64 + col];
        a0 += x0.x * w0 + x0.y * w1 + x0.z * w2 + x0.w * w3;
        a1 += x1.x * w0 + x1.y * w1 + x1.z * w2 + x1.w * w3;
        a2 += x2.x * w0 + x2.y * w1 + x2.z * w2 + x2.w * w3;
        a3 += x3.x * w0 + x3.y * w1 + x3.z * w2 + x3.w * w3;
    }
    const int nbase = blockIdx.x * 16 + sub * 4;
    h[(nbase + 0) * H_DIM + col] = a0;
    h[(nbase + 1) * H_DIM + col] = a1;
    h[(nbase + 2) * H_DIM + col] = a2;
    h[(nbase + 3) * H_DIM + col] = a3;
}

// ---------------- hedge aggregation (HALF-WARP per hyperedge, float4) -----
__global__ void __launch_bounds__(256) hedge_agg_kernel(const float *__restrict__ hin) {
    int he = blockIdx.x * 16 + (threadIdx.x >> 4);
    if (he >= N_HEDGES) return;
    int l16 = threadIdx.x & 15;
    int beg = g_hoff[he], end = g_hoff[he + 1];
    float4 acc = make_float4(0.f, 0.f, 0.f, 0.f);
    int m = beg;
    for (; m + 8 <= end; m += 8) {
        int n0 = g_csr_h[m],     n1 = g_csr_h[m + 1];
        int n2 = g_csr_h[m + 2], n3 = g_csr_h[m + 3];
        int n4 = g_csr_h[m + 4], n5 = g_csr_h[m + 5];
        int n6 = g_csr_h[m + 6], n7 = g_csr_h[m + 7];
        float4 v0 = *(const float4 *)(hin + n0 * H_DIM + l16 * 4);
        float4 v1 = *(const float4 *)(hin + n1 * H_DIM + l16 * 4);
        float4 v2 = *(const float4 *)(hin + n2 * H_DIM + l16 * 4);
        float4 v3 = *(const float4 *)(hin + n3 * H_DIM + l16 * 4);
        float4 v4 = *(const float4 *)(hin + n4 * H_DIM + l16 * 4);
        float4 v5 = *(const float4 *)(hin + n5 * H_DIM + l16 * 4);
        float4 v6 = *(const float4 *)(hin + n6 * H_DIM + l16 * 4);
        float4 v7 = *(const float4 *)(hin + n7 * H_DIM + l16 * 4);
        acc.x += ((v0.x + v1.x) + (v2.x + v3.x)) + ((v4.x + v5.x) + (v6.x + v7.x));
        acc.y += ((v0.y + v1.y) + (v2.y + v3.y)) + ((v4.y + v5.y) + (v6.y + v7.y));
        acc.z += ((v0.z + v1.z) + (v2.z + v3.z)) + ((v4.z + v5.z) + (v6.z + v7.z));
        acc.w += ((v0.w + v1.w) + (v2.w + v3.w)) + ((v4.w + v5.w) + (v6.w + v7.w));
    }
    for (; m + 4 <= end; m += 4) {
        int n0 = g_csr_h[m],     n1 = g_csr_h[m + 1];
        int n2 = g_csr_h[m + 2], n3 = g_csr_h[m + 3];
        float4 v0 = *(const float4 *)(hin + n0 * H_DIM + l16 * 4);
        float4 v1 = *(const float4 *)(hin + n1 * H_DIM + l16 * 4);
        float4 v2 = *(const float4 *)(hin + n2 * H_DIM + l16 * 4);
        float4 v3 = *(const float4 *)(hin + n3 * H_DIM + l16 * 4);
        acc.x += (v0.x + v1.x) + (v2.x + v3.x);
        acc.y += (v0.y + v1.y) + (v2.y + v3.y);
        acc.z += (v0.z + v1.z) + (v2.z + v3.z);
        acc.w += (v0.w + v1.w) + (v2.w + v3.w);
    }
    for (; m < end; m++) {
        int nd = g_csr_h[m];
        float4 v = *(const float4 *)(hin + nd * H_DIM + l16 * 4);
        acc.x += v.x; acc.y += v.y; acc.z += v.z; acc.w += v.w;
    }
    int deg = end - beg;
    float inv = 1.f / (float)(deg > 0 ? deg : 1);
    *(float4 *)(g_hxs + he * H_DIM + l16 * 4) =
        make_float4(acc.x * inv, acc.y * inv, acc.z * inv, acc.w * inv);
}

// ---------------- node aggregation (HALF-WARP per node, float4) ----------
// Mirror of hedge_agg (measured 22.8us, issue 58%): mean of incident
// g_hxs rows -> g_nodeagg.
__global__ void __launch_bounds__(256) node_agg_kernel() {
    int nd = blockIdx.x * 16 + (threadIdx.x >> 4);
    if (nd >= N_NODES) return;
    int l16 = threadIdx.x & 15;
    int beg = g_noff[nd], end = g_noff[nd + 1];
    float4 acc = make_float4(0.f, 0.f, 0.f, 0.f);
    int m = beg;
    for (; m + 8 <= end; m += 8) {
        int h0 = g_csr_n[m],     h1 = g_csr_n[m + 1];
        int h2 = g_csr_n[m + 2], h3 = g_csr_n[m + 3];
        int h4 = g_csr_n[m + 4], h5 = g_csr_n[m + 5];
        int h6 = g_csr_n[m + 6], h7 = g_csr_n[m + 7];
        float4 v0 = *(const float4 *)(g_hxs + h0 * H_DIM + l16 * 4);
        float4 v1 = *(const float4 *)(g_hxs + h1 * H_DIM + l16 * 4);
        float4 v2 = *(const float4 *)(g_hxs + h2 * H_DIM + l16 * 4);
        float4 v3 = *(const float4 *)(g_hxs + h3 * H_DIM + l16 * 4);
        float4 v4 = *(const float4 *)(g_hxs + h4 * H_DIM + l16 * 4);
        float4 v5 = *(const float4 *)(g_hxs + h5 * H_DIM + l16 * 4);
        float4 v6 = *(const float4 *)(g_hxs + h6 * H_DIM + l16 * 4);
        float4 v7 = *(const float4 *)(g_hxs + h7 * H_DIM + l16 * 4);
        acc.x += ((v0.x + v1.x) + (v2.x + v3.x)) + ((v4.x + v5.x) + (v6.x + v7.x));
        acc.y += ((v0.y + v1.y) + (v2.y + v3.y)) + ((v4.y + v5.y) + (v6.y + v7.y));
        acc.z += ((v0.z + v1.z) + (v2.z + v3.z)) + ((v4.z + v5.z) + (v6.z + v7.z));
        acc.w += ((v0.w + v1.w) + (v2.w + v3.w)) + ((v4.w + v5.w) + (v6.w + v7.w));
    }
    for (; m + 4 <= end; m += 4) {
        int h0 = g_csr_n[m],     h1 = g_csr_n[m + 1];
        int h2 = g_csr_n[m + 2], h3 = g_csr_n[m + 3];
        float4 v0 = *(const float4 *)(g_hxs + h0 * H_DIM + l16 * 4);
        float4 v1 = *(const float4 *)(g_hxs + h1 * H_DIM + l16 * 4);
        float4 v2 = *(const float4 *)(g_hxs + h2 * H_DIM + l16 * 4);
        float4 v3 = *(const float4 *)(g_hxs + h3 * H_DIM + l16 * 4);
        acc.x += (v0.x + v1.x) + (v2.x + v3.x);
        acc.y += (v0.y + v1.y) + (v2.y + v3.y);
        acc.z += (v0.z + v1.z) + (v2.z + v3.z);
        acc.w += (v0.w + v1.w) + (v2.w + v3.w);
    }
    for (; m < end; m++) {
        int he = g_csr_n[m];
        float4 v = *(const float4 *)(g_hxs + he * H_DIM + l16 * 4);
        acc.x += v.x; acc.y += v.y; acc.z += v.z; acc.w += v.w;
    }
    int deg = end - beg;
    float inv = 1.f / (float)(deg > 0 ? deg : 1);
    *(float4 *)(g_nodeagg + nd * H_DIM + l16 * 4) =
        make_float4(acc.x * inv, acc.y * inv, acc.z * inv, acc.w * inv);
}

// layer-invariant: per-node mean of incident hedge_attr rows
__global__ void __launch_bounds__(256) attr_agg_kernel(const float *__restrict__ hedge_attr) {
    int nd = blockIdx.x * 8 + (threadIdx.x >> 5);
    if (nd >= N_NODES) return;
    int lane = threadIdx.x & 31;
    int beg = g_noff[nd], end = g_noff[nd + 1];
    float a0 = 0.f, a1 = 0.f;
    for (int m = beg; m < end; m++) {
        int he = g_csr_n[m];
        const float *r = hedge_attr + he * HEDGE_DIM;
        a0 += r[lane];
        if (lane < 3) a1 += r[32 + lane];
    }
    int deg = end - beg;
    float inv = 1.f / (float)(deg > 0 ? deg : 1);
    g_attragg[nd * HEDGE_DIM + lane] = a0 * inv;
    if (lane < 3) g_attragg[nd * HEDGE_DIM + 32 + lane] = a1 * inv;
}

// ---------------- per-layer dual GEMM + activation (coalesced staging) ----
// 64-node tile, 256 threads (R12's winning GEMM core). Staging is now pure
// coalesced copies from h / g_attragg / g_nodeagg — no CSR gathers, no
// degree-dependent loops. Warp w stages nodes [8w, 8w+8).
#define GEMM_SMEM (64 * Z_PITCH * 4 + 32 * WK_PITCH * 4)   // 60416 B
__global__ void __launch_bounds__(256) gemm_act_kernel(
    const float *__restrict__ h_in,
    const float *__restrict__ Wf, const float *__restrict__ bf,
    const float *__restrict__ Wc, const float *__restrict__ bc,
    float *__restrict__ h_out) {
    extern __shared__ float sm[];
    float *z_s = sm;                      // [64][Z_PITCH]
    float *W_s = sm + 64 * Z_PITCH;       // [32][WK_PITCH] quarter-padded
    const int tid = threadIdx.x;
    const int nbase = blockIdx.x * 64;
    const int lane = tid & 31, w = tid >> 5;

    // ---- stage z: warp w covers nodes [8w, 8w+8)
    for (int i = 0; i < 8; i++) {
        int n = w * 8 + i;
        int node = nbase + n;
        float *zr = z_s + n * Z_PITCH;
        if (node < N_NODES) {
            int deg = g_noff[node + 1] - g_noff[node];
            int hl = lane & 15;
            if (lane < 16) {
                float4 hv = make_float4(0.f, 0.f, 0.f, 0.f);
                if (deg > 0)
                    hv = *(const float4 *)(h_in + node * H_DIM + hl * 4);
                *(float4 *)(zr + hl * 4) = hv;     // z[0..63]
            } else {
                float4 na = *(const float4 *)(g_nodeagg + node * H_DIM + hl * 4);
                zr[99 + hl * 4]     = na.x;        // z[99..162] (odd base)
                zr[99 + hl * 4 + 1] = na.y;
                zr[99 + hl * 4 + 2] = na.z;
                zr[99 + hl * 4 + 3] = na.w;
            }
            // attr z[64..98]
            if (lane < 32) zr[64 + lane] = g_attragg[node * HEDGE_DIM + lane];
            if (lane < 3)  zr[96 + lane] = g_attragg[node * HEDGE_DIM + 32 + lane];
        } else {
            for (int idx = lane; idx < Z_DIM; idx += 32) zr[idx] = 0.f;
        }
    }

    // ---- dual GEMM: thread -> (node nl, col quarter q)
    const int q = tid & 3;
    const int nl = tid >> 2;          // 0..63
    const int node = nbase + nl;

    ull acc[16];
#pragma unroll
    for (int i = 0; i < 16; i++) acc[i] = 0ull;

    for (int kb = 0; kb < Z_DIM; kb += 32) {
        int kc = (Z_DIM - kb < 32) ? (Z_DIM - kb) : 32;
        __syncthreads();
        for (int idx = tid; idx < kc * 128; idx += 256) {
            int k = idx >> 7, c = idx & 127;
            W_s[k * WK_PITCH + (c >> 5) * WQ_PITCH + (c & 31)] =
                (c < 64) ? Wf[(kb + k) * 64 + c] : Wc[(kb + k) * 64 + (c - 64)];
        }
        __syncthreads();
        for (int k = 0; k < kc; k++) {
            ull a = packdup(z_s[nl * Z_PITCH + kb + k]);
            const ulonglong2 *wr =
                (const ulonglong2 *)(W_s + k * WK_PITCH + q * WQ_PITCH);
#pragma unroll
            for (int i = 0; i < 8; i++) {
                ulonglong2 wp = wr[i];
                fma2(acc[2 * i],     a, wp.x);
                fma2(acc[2 * i + 1], a, wp.y);
            }
        }
    }

    // ---- epilogue: bias, pair f(q<2) with c(q+2) via shfl_xor(2), activate
    const float *bias = (q < 2) ? bf : bc;
    const int halfbase = (q & 1) * 32;
#pragma unroll
    for (int i = 0; i < 16; i++) {
        float2 y = unpk(acc[i]);
        int col = halfbase + 2 * i;
        y.x += bias[col];
        y.y += bias[col + 1];
        float ox = __shfl_xor_sync(0xffffffffu, y.x, 2);
        float oy = __shfl_xor_sync(0xffffffffu, y.y, 2);
        if (q < 2 && node < N_NODES) {
            int base = node * H_DIM + col;
            float o0 = sigmoidf(y.x) * softplusf(ox);
            float o1 = sigmoidf(y.y) * softplusf(oy);
            h_out[base]     = softplusf(o0 + h_in[base]);
            h_out[base + 1] = softplusf(o1 + h_in[base + 1]);
        }
    }
}

// ---------------- pooling + readout MLP (block per graph) ----------------
__global__ void __launch_bounds__(128) pool_mlp_kernel(
    const float *__restrict__ h, const int *__restrict__ batch,
    const float *__restrict__ Wp, const float *__restrict__ bp,
    const float *__restrict__ Wo, const float *__restrict__ bo,
    float *__restrict__ out) {
    int g = blockIdx.x;
    int tid = threadIdx.x;
    __shared__ int s_lo, s_hi;
    if (tid == 0) {
        int lo = 0, hi = N_NODES;
        while (lo < hi) { int mid = (lo + hi) >> 1; if (batch[mid] < g) lo = mid + 1; else hi = mid; }
        s_lo = lo;
    }
    if (tid == 1) {
        int lo = 0, hi = N_NODES;
        while (lo < hi) { int mid = (lo + hi) >> 1; if (batch[mid] < g + 1) lo = mid + 1; else hi = mid; }
        s_hi = lo;
    }
    __syncthreads();
    int lo = s_lo, hi = s_hi;
    int col = tid & 63, sub = tid >> 6;
    float acc = 0.f;
    for (int i = lo + sub; i < hi; i += 2) acc += h[i * H_DIM + col];
    __shared__ float gs[2][H_DIM];
    gs[sub][col] = acc;
    __syncthreads();
    __shared__ float gvec[H_DIM];
    if (tid < 64) {
        int cnt = hi - lo;
        gvec[tid] = (gs[0][tid] + gs[1][tid]) / (float)(cnt > 0 ? cnt : 1);
    }
    __syncthreads();
    float p = bp[tid];
#pragma unroll
    for (int k = 0; k < H_DIM; k++) p += gvec[k] * Wp[k * HOUT + tid];
    p = softplusf(p);
    float r = p * Wo[tid];
#pragma unroll
    for (int off = 16; off > 0; off >>= 1) r += __shfl_down_sync(0xffffffffu, r, off);
    __shared__ float red[4];
    if ((tid & 31) == 0) red[tid >> 5] = r;
    __syncthreads();
    if (tid == 0) out[g] = red[0] + red[1] + red[2] + red[3] + bo[0];
}

// ---------------- launch ----------------
// 4th launch = profiled slot -> NEW GEMM probe (444 blocks = 3/SM). It reads
// g_noff (fresh this pass) plus g_nodeagg/g_attragg/hA (previous pass's
// values — identical every replay; zeros on the very first pass). Its hB
// output is fully overwritten by the real layer-0 gemm.
extern "C" void kernel_launch(void *const *d_in, const int *in_sizes, int n_in,
                              void *d_out, int out_size) {
    const float *x          = (const float *)d_in[0];
    const float *hedge_attr = (const float *)d_in[1];
    const int   *node_idx   = (const int *)d_in[2];
    const int   *hedge_idx  = (const int *)d_in[3];
    const int   *batch      = (const int *)d_in[4];
    const float *W_embed    = (const float *)d_in[5];
    const float *b_embed    = (const float *)d_in[6];
    const float *Wf         = (const float *)d_in[7];
    const float *bf         = (const float *)d_in[8];
    const float *Wc         = (const float *)d_in[9];
    const float *bc         = (const float *)d_in[10];
    const float *Wp         = (const float *)d_in[11];
    const float *bp         = (const float *)d_in[12];
    const float *Wo         = (const float *)d_in[13];
    const float *bo         = (const float *)d_in[14];
    float *out = (float *)d_out;

    void *p_hA, *p_hB;
    cudaGetSymbolAddress(&p_hA, g_hA);
    cudaGetSymbolAddress(&p_hB, g_hB);
    float *hA = (float *)p_hA;
    float *hB = (float *)p_hB;

    cudaFuncSetAttribute(gemm_act_kernel,
                         cudaFuncAttributeMaxDynamicSharedMemorySize, GEMM_SMEM);

    // CSR build (counts arrive pre-zeroed: BSS init / fill_kernel tail)
    count_kernel<<<(E_INC + 255) / 256, 256>>>(node_idx, hedge_idx);       // 1
    scan_partial_both<<<NBT, 1024>>>();                                     // 2
    scan_final_both<<<NBT, 1024>>>();                                       // 3
    // PROBE (profiled slot): 444-block new gemm on stale-but-deterministic data
    gemm_act_kernel<<<444, 256, GEMM_SMEM>>>(hA, Wf, bf, Wc, bc, hB);       // 4
    fill_kernel<<<(E_INC + 255) / 256, 256>>>(node_idx, hedge_idx);         // 5
    embed_kernel<<<N_NODES / 16, 256>>>(x, W_embed, b_embed, hA);           // 6

    // layers (ping-pong hA/hB); attr_agg (layer-invariant) inside layer 0
    float *hcur = hA, *hnext = hB;
    for (int l = 0; l < N_LAYERS; l++) {
        hedge_agg_kernel<<<(N_HEDGES + 15) / 16, 256>>>(hcur);
        if (l == 0) attr_agg_kernel<<<(N_NODES + 7) / 8, 256>>>(hedge_attr);
        node_agg_kernel<<<(N_NODES + 15) / 16, 256>>>();
        gemm_act_kernel<<<(N_NODES + 63) / 64, 256, GEMM_SMEM>>>(
            hcur,
            Wf + (size_t)l * Z_DIM * H_DIM, bf + (size_t)l * H_DIM,
            Wc + (size_t)l * Z_DIM * H_DIM, bc + (size_t)l * H_DIM,
            hnext);
        float *t = hcur; hcur = hnext; hnext = t;
    }

    // pooling + readout
    pool_mlp_kernel<<<N_GRAPHS, 128>>>(hcur, batch, Wp, bp, Wo, bo, out);
}

// round 16
// speedup vs baseline: 1.5652x; 1.5652x over previous
#include <cuda_runtime.h>
#include <cuda_bf16.h>
#include <math.h>

#define N_NODES   50000
#define N_HEDGES  100000
#define E_INC     800000
#define N_GRAPHS  512
#define IN_DIM    92
#define H_DIM     64
#define HOUT      128
#define HEDGE_DIM 35
#define Z_DIM     163   // 64 + 35 + 64 (logical)
#define Z_PITCH   164   // padded smem row pitch (16B-aligned rows)
#define N_LAYERS  3

#define NBH 98            // ceil(100000/1024)
#define NBN 49            // ceil(50000/1024)
#define NBT (NBH + NBN)   // 147

typedef unsigned long long ull;

// ---------------- scratch (device globals; no allocation allowed) ----------
__device__ float g_hA[N_NODES * H_DIM];
__device__ float g_hB[N_NODES * H_DIM];
__device__ float g_hxs[N_HEDGES * H_DIM];
__device__ float g_nodeagg[N_NODES * H_DIM];
__device__ float g_attragg[N_NODES * HEDGE_DIM];

__device__ int g_hcnt[N_HEDGES];
__device__ int g_ncnt[N_NODES];
__device__ int g_hoff[N_HEDGES + 1];
__device__ int g_noff[N_NODES + 1];
__device__ int g_hfill[N_HEDGES];
__device__ int g_nfill[N_NODES];
__device__ int g_csr_h[E_INC];   // node ids grouped by hedge
__device__ int g_csr_n[E_INC];   // hedge ids grouped by node
__device__ int g_part[256];

// ---------------- helpers ----------------
__device__ __forceinline__ float softplusf(float x) {
    return fmaxf(x, 0.f) + log1pf(expf(-fabsf(x)));
}
__device__ __forceinline__ float sigmoidf(float x) {
    return 1.f / (1.f + expf(-x));
}
__device__ __forceinline__ ull packdup(float x) {
    ull r;
    asm("mov.b64 %0, {%1, %2};" : "=l"(r)
        : "r"(__float_as_uint(x)), "r"(__float_as_uint(x)));
    return r;
}
__device__ __forceinline__ float2 unpk(ull v) {
    unsigned a, b;
    asm("mov.b64 {%0, %1}, %2;" : "=r"(a), "=r"(b) : "l"(v));
    return make_float2(__uint_as_float(a), __uint_as_float(b));
}
__device__ __forceinline__ void fma2(ull &c, ull a, ull b) {
    asm("fma.rn.f32x2 %0, %1, %2, %0;" : "+l"(c) : "l"(a), "l"(b));
}

// ---------------- CSR construction ----------------
__global__ void count_kernel(const int *__restrict__ node_idx,
                             const int *__restrict__ hedge_idx) {
    int e = blockIdx.x * blockDim.x + threadIdx.x;
    if (e < E_INC) {
        atomicAdd(&g_hcnt[hedge_idx[e]], 1);
        atomicAdd(&g_ncnt[node_idx[e]], 1);
    }
}

__global__ void __launch_bounds__(1024) scan_partial_both() {
    __shared__ int s[1024];
    int b = blockIdx.x;
    const int *cnt = (b < NBH) ? g_hcnt : g_ncnt;
    int n = (b < NBH) ? N_HEDGES : N_NODES;
    int chunk = (b < NBH) ? b : b - NBH;
    int i = chunk * 1024 + threadIdx.x;
    s[threadIdx.x] = (i < n) ? cnt[i] : 0;
    __syncthreads();
    for (int d = 512; d > 0; d >>= 1) {
        if (threadIdx.x < d) s[threadIdx.x] += s[threadIdx.x + d];
        __syncthreads();
    }
    if (threadIdx.x == 0) g_part[b] = s[0];
}

__global__ void __launch_bounds__(1024) scan_final_both() {
    __shared__ int s[1024];
    __shared__ int red[32];
    __shared__ int sbase;
    int b = blockIdx.x;
    bool isH = b < NBH;
    const int *cnt = isH ? g_hcnt : g_ncnt;
    int *off  = isH ? g_hoff : g_noff;
    int *fill = isH ? g_hfill : g_nfill;
    int n     = isH ? N_HEDGES : N_NODES;
    int start = isH ? 0 : NBH;
    int chunk = isH ? b : b - NBH;
    int t = threadIdx.x;

    int contrib = (t < NBT && t >= start && t < b) ? g_part[t] : 0;
#pragma unroll
    for (int o = 16; o > 0; o >>= 1)
        contrib += __shfl_down_sync(0xffffffffu, contrib, o);
    if ((t & 31) == 0) red[t >> 5] = contrib;
    __syncthreads();
    if (t == 0) {
        int acc = 0;
#pragma unroll
        for (int i = 0; i < 32; i++) acc += red[i];
        sbase = acc;
    }
    __syncthreads();

    int i = chunk * 1024 + t;
    int v = (i < n) ? cnt[i] : 0;
    s[t] = v;
    __syncthreads();
    for (int d = 1; d < 1024; d <<= 1) {
        int x = (t >= d) ? s[t - d] : 0;
        __syncthreads();
        s[t] += x;
        __syncthreads();
    }
    int excl = s[t] - v + sbase;
    if (i < n) {
        off[i] = excl;
        fill[i] = excl;
        if (i == n - 1) off[n] = excl + v;
    }
}

__global__ void fill_kernel(const int *__restrict__ node_idx,
                            const int *__restrict__ hedge_idx) {
    int e = blockIdx.x * blockDim.x + threadIdx.x;
    if (e < E_INC) {
        int nd = node_idx[e], he = hedge_idx[e];
        int p = atomicAdd(&g_hfill[he], 1);
        g_csr_h[p] = nd;
        int p2 = atomicAdd(&g_nfill[nd], 1);
        g_csr_n[p2] = he;
        if (e < N_HEDGES) g_hcnt[e] = 0;
        if (e < N_NODES)  g_ncnt[e] = 0;
    }
}

// ---------------- embed: h = x @ W_embed + b (conflict-free smem) ---------
__global__ void __launch_bounds__(256) embed_kernel(
    const float *__restrict__ x, const float *__restrict__ W,
    const float *__restrict__ b, float *__restrict__ h) {
    __shared__ float W_s[IN_DIM * H_DIM];
    __shared__ float x_s[16][IN_DIM];
    const int tid = threadIdx.x;
    for (int i = tid; i < IN_DIM * H_DIM; i += 256) W_s[i] = W[i];
    {
        const int nbase = blockIdx.x * 16;
        for (int idx = tid; idx < 16 * 23; idx += 256) {
            int n = idx / 23, k4 = idx - n * 23;
            *(float4 *)(&x_s[n][k4 * 4]) =
                *(const float4 *)(x + (nbase + n) * IN_DIM + k4 * 4);
        }
    }
    __syncthreads();
    const int col = tid & 63, sub = tid >> 6;
    float a0, a1, a2, a3;
    a0 = a1 = a2 = a3 = b[col];
#pragma unroll
    for (int k4 = 0; k4 < 23; k4++) {
        float4 x0 = *(const float4 *)(&x_s[sub * 4 + 0][k4 * 4]);
        float4 x1 = *(const float4 *)(&x_s[sub * 4 + 1][k4 * 4]);
        float4 x2 = *(const float4 *)(&x_s[sub * 4 + 2][k4 * 4]);
        float4 x3 = *(const float4 *)(&x_s[sub * 4 + 3][k4 * 4]);
        float w0 = W_s[(k4 * 4 + 0) * 64 + col];
        float w1 = W_s[(k4 * 4 + 1) * 64 + col];
        float w2 = W_s[(k4 * 4 + 2) * 64 + col];
        float w3 = W_s[(k4 * 4 + 3) * 64 + col];
        a0 += x0.x * w0 + x0.y * w1 + x0.z * w2 + x0.w * w3;
        a1 += x1.x * w0 + x1.y * w1 + x1.z * w2 + x1.w * w3;
        a2 += x2.x * w0 + x2.y * w1 + x2.z * w2 + x2.w * w3;
        a3 += x3.x * w0 + x3.y * w1 + x3.z * w2 + x3.w * w3;
    }
    const int nbase = blockIdx.x * 16 + sub * 4;
    h[(nbase + 0) * H_DIM + col] = a0;
    h[(nbase + 1) * H_DIM + col] = a1;
    h[(nbase + 2) * H_DIM + col] = a2;
    h[(nbase + 3) * H_DIM + col] = a3;
}

// ---------------- hedge aggregation (HALF-WARP per hyperedge, float4) -----
__global__ void __launch_bounds__(256) hedge_agg_kernel(const float *__restrict__ hin) {
    int he = blockIdx.x * 16 + (threadIdx.x >> 4);
    if (he >= N_HEDGES) return;
    int l16 = threadIdx.x & 15;
    int beg = g_hoff[he], end = g_hoff[he + 1];
    float4 acc = make_float4(0.f, 0.f, 0.f, 0.f);
    int m = beg;
    for (; m + 8 <= end; m += 8) {
        int n0 = g_csr_h[m],     n1 = g_csr_h[m + 1];
        int n2 = g_csr_h[m + 2], n3 = g_csr_h[m + 3];
        int n4 = g_csr_h[m + 4], n5 = g_csr_h[m + 5];
        int n6 = g_csr_h[m + 6], n7 = g_csr_h[m + 7];
        float4 v0 = *(const float4 *)(hin + n0 * H_DIM + l16 * 4);
        float4 v1 = *(const float4 *)(hin + n1 * H_DIM + l16 * 4);
        float4 v2 = *(const float4 *)(hin + n2 * H_DIM + l16 * 4);
        float4 v3 = *(const float4 *)(hin + n3 * H_DIM + l16 * 4);
        float4 v4 = *(const float4 *)(hin + n4 * H_DIM + l16 * 4);
        float4 v5 = *(const float4 *)(hin + n5 * H_DIM + l16 * 4);
        float4 v6 = *(const float4 *)(hin + n6 * H_DIM + l16 * 4);
        float4 v7 = *(const float4 *)(hin + n7 * H_DIM + l16 * 4);
        acc.x += ((v0.x + v1.x) + (v2.x + v3.x)) + ((v4.x + v5.x) + (v6.x + v7.x));
        acc.y += ((v0.y + v1.y) + (v2.y + v3.y)) + ((v4.y + v5.y) + (v6.y + v7.y));
        acc.z += ((v0.z + v1.z) + (v2.z + v3.z)) + ((v4.z + v5.z) + (v6.z + v7.z));
        acc.w += ((v0.w + v1.w) + (v2.w + v3.w)) + ((v4.w + v5.w) + (v6.w + v7.w));
    }
    for (; m + 4 <= end; m += 4) {
        int n0 = g_csr_h[m],     n1 = g_csr_h[m + 1];
        int n2 = g_csr_h[m + 2], n3 = g_csr_h[m + 3];
        float4 v0 = *(const float4 *)(hin + n0 * H_DIM + l16 * 4);
        float4 v1 = *(const float4 *)(hin + n1 * H_DIM + l16 * 4);
        float4 v2 = *(const float4 *)(hin + n2 * H_DIM + l16 * 4);
        float4 v3 = *(const float4 *)(hin + n3 * H_DIM + l16 * 4);
        acc.x += (v0.x + v1.x) + (v2.x + v3.x);
        acc.y += (v0.y + v1.y) + (v2.y + v3.y);
        acc.z += (v0.z + v1.z) + (v2.z + v3.z);
        acc.w += (v0.w + v1.w) + (v2.w + v3.w);
    }
    for (; m < end; m++) {
        int nd = g_csr_h[m];
        float4 v = *(const float4 *)(hin + nd * H_DIM + l16 * 4);
        acc.x += v.x; acc.y += v.y; acc.z += v.z; acc.w += v.w;
    }
    int deg = end - beg;
    float inv = 1.f / (float)(deg > 0 ? deg : 1);
    *(float4 *)(g_hxs + he * H_DIM + l16 * 4) =
        make_float4(acc.x * inv, acc.y * inv, acc.z * inv, acc.w * inv);
}

// ---------------- node aggregation (HALF-WARP per node, float4) ----------
__global__ void __launch_bounds__(256) node_agg_kernel() {
    int nd = blockIdx.x * 16 + (threadIdx.x >> 4);
    if (nd >= N_NODES) return;
    int l16 = threadIdx.x & 15;
    int beg = g_noff[nd], end = g_noff[nd + 1];
    float4 acc = make_float4(0.f, 0.f, 0.f, 0.f);
    int m = beg;
    for (; m + 8 <= end; m += 8) {
        int h0 = g_csr_n[m],     h1 = g_csr_n[m + 1];
        int h2 = g_csr_n[m + 2], h3 = g_csr_n[m + 3];
        int h4 = g_csr_n[m + 4], h5 = g_csr_n[m + 5];
        int h6 = g_csr_n[m + 6], h7 = g_csr_n[m + 7];
        float4 v0 = *(const float4 *)(g_hxs + h0 * H_DIM + l16 * 4);
        float4 v1 = *(const float4 *)(g_hxs + h1 * H_DIM + l16 * 4);
        float4 v2 = *(const float4 *)(g_hxs + h2 * H_DIM + l16 * 4);
        float4 v3 = *(const float4 *)(g_hxs + h3 * H_DIM + l16 * 4);
        float4 v4 = *(const float4 *)(g_hxs + h4 * H_DIM + l16 * 4);
        float4 v5 = *(const float4 *)(g_hxs + h5 * H_DIM + l16 * 4);
        float4 v6 = *(const float4 *)(g_hxs + h6 * H_DIM + l16 * 4);
        float4 v7 = *(const float4 *)(g_hxs + h7 * H_DIM + l16 * 4);
        acc.x += ((v0.x + v1.x) + (v2.x + v3.x)) + ((v4.x + v5.x) + (v6.x + v7.x));
        acc.y += ((v0.y + v1.y) + (v2.y + v3.y)) + ((v4.y + v5.y) + (v6.y + v7.y));
        acc.z += ((v0.z + v1.z) + (v2.z + v3.z)) + ((v4.z + v5.z) + (v6.z + v7.z));
        acc.w += ((v0.w + v1.w) + (v2.w + v3.w)) + ((v4.w + v5.w) + (v6.w + v7.w));
    }
    for (; m + 4 <= end; m += 4) {
        int h0 = g_csr_n[m],     h1 = g_csr_n[m + 1];
        int h2 = g_csr_n[m + 2], h3 = g_csr_n[m + 3];
        float4 v0 = *(const float4 *)(g_hxs + h0 * H_DIM + l16 * 4);
        float4 v1 = *(const float4 *)(g_hxs + h1 * H_DIM + l16 * 4);
        float4 v2 = *(const float4 *)(g_hxs + h2 * H_DIM + l16 * 4);
        float4 v3 = *(const float4 *)(g_hxs + h3 * H_DIM + l16 * 4);
        acc.x += (v0.x + v1.x) + (v2.x + v3.x);
        acc.y += (v0.y + v1.y) + (v2.y + v3.y);
        acc.z += (v0.z + v1.z) + (v2.z + v3.z);
        acc.w += (v0.w + v1.w) + (v2.w + v3.w);
    }
    for (; m < end; m++) {
        int he = g_csr_n[m];
        float4 v = *(const float4 *)(g_hxs + he * H_DIM + l16 * 4);
        acc.x += v.x; acc.y += v.y; acc.z += v.z; acc.w += v.w;
    }
    int deg = end - beg;
    float inv = 1.f / (float)(deg > 0 ? deg : 1);
    *(float4 *)(g_nodeagg + nd * H_DIM + l16 * 4) =
        make_float4(acc.x * inv, acc.y * inv, acc.z * inv, acc.w * inv);
}

// layer-invariant: per-node mean of incident hedge_attr rows
__global__ void __launch_bounds__(256) attr_agg_kernel(const float *__restrict__ hedge_attr) {
    int nd = blockIdx.x * 8 + (threadIdx.x >> 5);
    if (nd >= N_NODES) return;
    int lane = threadIdx.x & 31;
    int beg = g_noff[nd], end = g_noff[nd + 1];
    float a0 = 0.f, a1 = 0.f;
    for (int m = beg; m < end; m++) {
        int he = g_csr_n[m];
        const float *r = hedge_attr + he * HEDGE_DIM;
        a0 += r[lane];
        if (lane < 3) a1 += r[32 + lane];
    }
    int deg = end - beg;
    float inv = 1.f / (float)(deg > 0 ? deg : 1);
    g_attragg[nd * HEDGE_DIM + lane] = a0 * inv;
    if (lane < 3) g_attragg[nd * HEDGE_DIM + 32 + lane] = a1 * inv;
}

// ---------------- per-layer dual GEMM + activation (unique-byte LDS) ------
// 64-node tile, 256 threads. Mapping: warp w -> nodes [8w, 8w+8); lane L ->
// combined cols [4L, 4L+4) (L<16: Wf cols 4L.., L>=16: Wc cols 4(L-16)..).
// Per k: ONE warp LDS.128 (W row contiguous 512B, all bytes unique,
// conflict-free) + 8 broadcast z loads + 16 fma2.
#define GEMM_SMEM (64 * Z_PITCH * 4 + 32 * 128 * 4)   // 41984+16384 = 58368 B
__global__ void __launch_bounds__(256) gemm_act_kernel(
    const float *__restrict__ h_in,
    const float *__restrict__ Wf, const float *__restrict__ bf,
    const float *__restrict__ Wc, const float *__restrict__ bc,
    float *__restrict__ h_out) {
    extern __shared__ float sm[];
    float *z_s = sm;                      // [64][Z_PITCH]
    float *W_s = sm + 64 * Z_PITCH;       // [32][128] combined cols
    const int tid = threadIdx.x;
    const int nbase = blockIdx.x * 64;
    const int lane = tid & 31, w = tid >> 5;

    // ---- stage z: warp w covers nodes [8w, 8w+8) (coalesced copies)
    for (int i = 0; i < 8; i++) {
        int n = w * 8 + i;
        int node = nbase + n;
        float *zr = z_s + n * Z_PITCH;
        if (node < N_NODES) {
            int deg = g_noff[node + 1] - g_noff[node];
            int hl = lane & 15;
            if (lane < 16) {
                float4 hv = make_float4(0.f, 0.f, 0.f, 0.f);
                if (deg > 0)
                    hv = *(const float4 *)(h_in + node * H_DIM + hl * 4);
                *(float4 *)(zr + hl * 4) = hv;     // z[0..63]
            } else {
                float4 na = *(const float4 *)(g_nodeagg + node * H_DIM + hl * 4);
                zr[99 + hl * 4]     = na.x;        // z[99..162] (odd base)
                zr[99 + hl * 4 + 1] = na.y;
                zr[99 + hl * 4 + 2] = na.z;
                zr[99 + hl * 4 + 3] = na.w;
            }
            zr[64 + lane] = g_attragg[node * HEDGE_DIM + lane];      // z[64..95]
            if (lane < 3) zr[96 + lane] = g_attragg[node * HEDGE_DIM + 32 + lane];
        } else {
            for (int idx = lane; idx < Z_DIM; idx += 32) zr[idx] = 0.f;
        }
    }

    // ---- GEMM: lane L -> combined cols [4L, 4L+4), 8 nodes per warp
    ull acc[8][2];
#pragma unroll
    for (int n = 0; n < 8; n++) { acc[n][0] = 0ull; acc[n][1] = 0ull; }

    const int zrow = w * 8;
    for (int kb = 0; kb < Z_DIM; kb += 32) {
        int kc = (Z_DIM - kb < 32) ? (Z_DIM - kb) : 32;
        __syncthreads();
        for (int idx = tid; idx < kc * 128; idx += 256) {
            int k = idx >> 7, c = idx & 127;
            W_s[k * 128 + c] = (c < 64) ? Wf[(kb + k) * 64 + c]
                                        : Wc[(kb + k) * 64 + (c - 64)];
        }
        __syncthreads();
        for (int k = 0; k < kc; k++) {
            ulonglong2 wp = *(const ulonglong2 *)(W_s + k * 128 + lane * 4);
#pragma unroll
            for (int n = 0; n < 8; n++) {
                ull a = packdup(z_s[(zrow + n) * Z_PITCH + kb + k]);
                fma2(acc[n][0], a, wp.x);
                fma2(acc[n][1], a, wp.y);
            }
        }
    }

    // ---- epilogue: lane L<16 holds f cols 4L..4L+3; lane L+16 the matching
    // c cols. Pair via shfl_xor(16); 16 lanes activate + store float4.
    const float *bias = (lane < 16) ? (bf + 4 * lane) : (bc + 4 * (lane - 16));
    float b0 = bias[0], b1 = bias[1], b2 = bias[2], b3 = bias[3];
#pragma unroll
    for (int n = 0; n < 8; n++) {
        int node = nbase + zrow + n;
        float2 ya = unpk(acc[n][0]);
        float2 yb = unpk(acc[n][1]);
        float y0 = ya.x + b0, y1 = ya.y + b1, y2 = yb.x + b2, y3 = yb.y + b3;
        float c0 = __shfl_xor_sync(0xffffffffu, y0, 16);
        float c1 = __shfl_xor_sync(0xffffffffu, y1, 16);
        float c2 = __shfl_xor_sync(0xffffffffu, y2, 16);
        float c3 = __shfl_xor_sync(0xffffffffu, y3, 16);
        if (lane < 16 && node < N_NODES) {
            float4 hr = *(const float4 *)(h_in + node * H_DIM + 4 * lane);
            float4 o;
            o.x = softplusf(sigmoidf(y0) * softplusf(c0) + hr.x);
            o.y = softplusf(sigmoidf(y1) * softplusf(c1) + hr.y);
            o.z = softplusf(sigmoidf(y2) * softplusf(c2) + hr.z);
            o.w = softplusf(sigmoidf(y3) * softplusf(c3) + hr.w);
            *(float4 *)(h_out + node * H_DIM + 4 * lane) = o;
        }
    }
}

// ---------------- pooling + readout MLP (block per graph) ----------------
__global__ void __launch_bounds__(128) pool_mlp_kernel(
    const float *__restrict__ h, const int *__restrict__ batch,
    const float *__restrict__ Wp, const float *__restrict__ bp,
    const float *__restrict__ Wo, const float *__restrict__ bo,
    float *__restrict__ out) {
    int g = blockIdx.x;
    int tid = threadIdx.x;
    __shared__ int s_lo, s_hi;
    if (tid == 0) {
        int lo = 0, hi = N_NODES;
        while (lo < hi) { int mid = (lo + hi) >> 1; if (batch[mid] < g) lo = mid + 1; else hi = mid; }
        s_lo = lo;
    }
    if (tid == 1) {
        int lo = 0, hi = N_NODES;
        while (lo < hi) { int mid = (lo + hi) >> 1; if (batch[mid] < g + 1) lo = mid + 1; else hi = mid; }
        s_hi = lo;
    }
    __syncthreads();
    int lo = s_lo, hi = s_hi;
    int col = tid & 63, sub = tid >> 6;
    float acc = 0.f;
    for (int i = lo + sub; i < hi; i += 2) acc += h[i * H_DIM + col];
    __shared__ float gs[2][H_DIM];
    gs[sub][col] = acc;
    __syncthreads();
    __shared__ float gvec[H_DIM];
    if (tid < 64) {
        int cnt = hi - lo;
        gvec[tid] = (gs[0][tid] + gs[1][tid]) / (float)(cnt > 0 ? cnt : 1);
    }
    __syncthreads();
    float p = bp[tid];
#pragma unroll
    for (int k = 0; k < H_DIM; k++) p += gvec[k] * Wp[k * HOUT + tid];
    p = softplusf(p);
    float r = p * Wo[tid];
#pragma unroll
    for (int off = 16; off > 0; off >>= 1) r += __shfl_down_sync(0xffffffffu, r, off);
    __shared__ float red[4];
    if ((tid & 31) == 0) red[tid >> 5] = r;
    __syncthreads();
    if (tid == 0) out[g] = red[0] + red[1] + red[2] + red[3] + bo[0];
}

// ---------------- launch ----------------
// 4th launch = profiled slot -> NEW GEMM probe (444 blocks = 3/SM) on
// stale-but-deterministic data (g_noff fresh; nodeagg/attragg/hA = previous
// pass, identical every replay, zeros on very first pass). Its hB output is
// fully overwritten by the real layer-0 gemm.
extern "C" void kernel_launch(void *const *d_in, const int *in_sizes, int n_in,
                              void *d_out, int out_size) {
    const float *x          = (const float *)d_in[0];
    const float *hedge_attr = (const float *)d_in[1];
    const int   *node_idx   = (const int *)d_in[2];
    const int   *hedge_idx  = (const int *)d_in[3];
    const int   *batch      = (const int *)d_in[4];
    const float *W_embed    = (const float *)d_in[5];
    const float *b_embed    = (const float *)d_in[6];
    const float *Wf         = (const float *)d_in[7];
    const float *bf         = (const float *)d_in[8];
    const float *Wc         = (const float *)d_in[9];
    const float *bc         = (const float *)d_in[10];
    const float *Wp         = (const float *)d_in[11];
    const float *bp         = (const float *)d_in[12];
    const float *Wo         = (const float *)d_in[13];
    const float *bo         = (const float *)d_in[14];
    float *out = (float *)d_out;

    void *p_hA, *p_hB;
    cudaGetSymbolAddress(&p_hA, g_hA);
    cudaGetSymbolAddress(&p_hB, g_hB);
    float *hA = (float *)p_hA;
    float *hB = (float *)p_hB;

    cudaFuncSetAttribute(gemm_act_kernel,
                         cudaFuncAttributeMaxDynamicSharedMemorySize, GEMM_SMEM);

    // CSR build (counts arrive pre-zeroed: BSS init / fill_kernel tail)
    count_kernel<<<(E_INC + 255) / 256, 256>>>(node_idx, hedge_idx);       // 1
    scan_partial_both<<<NBT, 1024>>>();                                     // 2
    scan_final_both<<<NBT, 1024>>>();                                       // 3
    // PROBE (profiled slot): 444-block new gemm on stale-but-deterministic data
    gemm_act_kernel<<<444, 256, GEMM_SMEM>>>(hA, Wf, bf, Wc, bc, hB);       // 4
    fill_kernel<<<(E_INC + 255) / 256, 256>>>(node_idx, hedge_idx);         // 5
    embed_kernel<<<N_NODES / 16, 256>>>(x, W_embed, b_embed, hA);           // 6

    // layers (ping-pong hA/hB); attr_agg (layer-invariant) inside layer 0
    float *hcur = hA, *hnext = hB;
    for (int l = 0; l < N_LAYERS; l++) {
        hedge_agg_kernel<<<(N_HEDGES + 15) / 16, 256>>>(hcur);
        if (l == 0) attr_agg_kernel<<<(N_NODES + 7) / 8, 256>>>(hedge_attr);
        node_agg_kernel<<<(N_NODES + 15) / 16, 256>>>();
        gemm_act_kernel<<<(N_NODES + 63) / 64, 256, GEMM_SMEM>>>(
            hcur,
            Wf + (size_t)l * Z_DIM * H_DIM, bf + (size_t)l * H_DIM,
            Wc + (size_t)l * Z_DIM * H_DIM, bc + (size_t)l * H_DIM,
            hnext);
        float *t = hcur; hcur = hnext; hnext = t;
    }

    // pooling + readout
    pool_mlp_kernel<<<N_GRAPHS, 128>>>(hcur, batch, Wp, bp, Wo, bo, out);
}